// round 1
// baseline (speedup 1.0000x reference)
#include <cuda_runtime.h>
#include <math.h>

#define VOCAB 50257
#define HID   1024
#define H2    2048
#define MAXLEN 64
#define GEMV_BLOCKS 296
#define BIG_NEG (-3.0e38f)

// ---------------- scratch (no allocation allowed) ----------------
__device__ float g_logits[MAXLEN];
__device__ float g_w[MAXLEN];
__device__ float g_cat[H2];       // [embedded, attn_applied]
__device__ float g_x[HID];        // relu(combine)
__device__ float g_h[HID];        // h_new
__device__ float g_pm[GEMV_BLOCKS];
__device__ float g_ps[GEMV_BLOCKS];
__device__ float g_lse;

__device__ __forceinline__ float warp_sum(float v) {
#pragma unroll
    for (int o = 16; o; o >>= 1) v += __shfl_xor_sync(0xffffffffu, v, o);
    return v;
}

__device__ __forceinline__ void lse_update(float& m, float& s, float x) {
    float M = fmaxf(m, x);
    s = s * expf(m - M) + expf(x - M);
    m = M;
}

// ---------------- K1: attention logits (64 rows x 2048 dot) ----------------
__global__ void k_attn_logits(const int* __restrict__ inp,
                              const float* __restrict__ hidden,
                              const float* __restrict__ emb,
                              const float* __restrict__ attn_W,
                              const float* __restrict__ attn_b) {
    int row = blockIdx.x;
    int t = threadIdx.x;
    const float* er = emb + (size_t)inp[0] * HID;
    const float* wr = attn_W + (size_t)row * H2;
    float acc = 0.f;
    for (int j = t; j < H2; j += 256) {
        float v = (j < HID) ? er[j] : hidden[j - HID];
        acc += wr[j] * v;
    }
    acc = warp_sum(acc);
    __shared__ float s[8];
    if ((t & 31) == 0) s[t >> 5] = acc;
    __syncthreads();
    if (t == 0) {
        float a = 0.f;
#pragma unroll
        for (int i = 0; i < 8; i++) a += s[i];
        g_logits[row] = a + attn_b[row];
    }
}

// ---------------- K2: softmax over 64 logits ----------------
__global__ void k_softmax(float* __restrict__ dout) {
    int t = threadIdx.x;  // 64 threads
    float x = g_logits[t];
    __shared__ float sm[64];
    sm[t] = x;
    __syncthreads();
    for (int o = 32; o; o >>= 1) {
        if (t < o) sm[t] = fmaxf(sm[t], sm[t + o]);
        __syncthreads();
    }
    float m = sm[0];
    __syncthreads();
    float e = expf(x - m);
    sm[t] = e;
    __syncthreads();
    for (int o = 32; o; o >>= 1) {
        if (t < o) sm[t] += sm[t + o];
        __syncthreads();
    }
    float w = e / sm[0];
    g_w[t] = w;
    dout[VOCAB + HID + t] = w;  // attn_weights output
}

// ---------------- K3: attn_applied + build cat vector ----------------
__global__ void k_applied(const int* __restrict__ inp,
                          const float* __restrict__ emb,
                          const float* __restrict__ enc) {
    int j = blockIdx.x * blockDim.x + threadIdx.x;  // 0..1023
    __shared__ float sw[MAXLEN];
    if (threadIdx.x < MAXLEN) sw[threadIdx.x] = g_w[threadIdx.x];
    __syncthreads();
    float a = 0.f;
#pragma unroll 8
    for (int i = 0; i < MAXLEN; i++) a += sw[i] * enc[i * HID + j];
    g_cat[HID + j] = a;
    g_cat[j] = emb[(size_t)inp[0] * HID + j];
}

// ---------------- K4: combine GEMV + relu (1024 rows x 2048) ----------------
__global__ void __launch_bounds__(256) k_combine(const float* __restrict__ comb_W,
                                                 const float* __restrict__ comb_b) {
    __shared__ float4 sc[H2 / 4];
    int t = threadIdx.x;
    const float4* gc = (const float4*)g_cat;
    for (int i = t; i < H2 / 4; i += 256) sc[i] = gc[i];
    __syncthreads();
    int wid = t >> 5, lane = t & 31;
    int row = blockIdx.x * 8 + wid;
    const float4* wr = (const float4*)(comb_W + (size_t)row * H2);
    float acc = 0.f;
#pragma unroll
    for (int i = 0; i < 16; i++) {
        float4 w4 = wr[lane + 32 * i];
        float4 v4 = sc[lane + 32 * i];
        acc += w4.x * v4.x + w4.y * v4.y + w4.z * v4.z + w4.w * v4.w;
    }
    acc = warp_sum(acc);
    if (lane == 0) g_x[row] = fmaxf(acc + comb_b[row], 0.f);
}

// ---------------- K5: fused GRU step (warp per output element) ----------------
__global__ void __launch_bounds__(256) k_gru(const float* __restrict__ Wih,
                                             const float* __restrict__ Whh,
                                             const float* __restrict__ bih,
                                             const float* __restrict__ bhh,
                                             const float* __restrict__ hidden,
                                             float* __restrict__ dout) {
    __shared__ float4 sx[HID / 4];
    __shared__ float4 sh[HID / 4];
    int t = threadIdx.x;
    const float4* gx = (const float4*)g_x;
    const float4* gh4 = (const float4*)hidden;
    for (int i = t; i < HID / 4; i += 256) {
        sx[i] = gx[i];
        sh[i] = gh4[i];
    }
    __syncthreads();
    int wid = t >> 5, lane = t & 31;
    int k = blockIdx.x * 8 + wid;
    const float4* wir = (const float4*)(Wih + (size_t)k * HID);
    const float4* wiz = (const float4*)(Wih + (size_t)(k + HID) * HID);
    const float4* win = (const float4*)(Wih + (size_t)(k + 2 * HID) * HID);
    const float4* whr = (const float4*)(Whh + (size_t)k * HID);
    const float4* whz = (const float4*)(Whh + (size_t)(k + HID) * HID);
    const float4* whn = (const float4*)(Whh + (size_t)(k + 2 * HID) * HID);
    float air = 0, aiz = 0, ain = 0, ahr = 0, ahz = 0, ahn = 0;
#pragma unroll
    for (int i = 0; i < 8; i++) {
        int off = lane + 32 * i;
        float4 xv = sx[off], hv = sh[off];
        float4 a;
        a = wir[off]; air += a.x * xv.x + a.y * xv.y + a.z * xv.z + a.w * xv.w;
        a = wiz[off]; aiz += a.x * xv.x + a.y * xv.y + a.z * xv.z + a.w * xv.w;
        a = win[off]; ain += a.x * xv.x + a.y * xv.y + a.z * xv.z + a.w * xv.w;
        a = whr[off]; ahr += a.x * hv.x + a.y * hv.y + a.z * hv.z + a.w * hv.w;
        a = whz[off]; ahz += a.x * hv.x + a.y * hv.y + a.z * hv.z + a.w * hv.w;
        a = whn[off]; ahn += a.x * hv.x + a.y * hv.y + a.z * hv.z + a.w * hv.w;
    }
    air = warp_sum(air);
    aiz = warp_sum(aiz);
    ain = warp_sum(ain);
    ahr = warp_sum(ahr);
    ahz = warp_sum(ahz);
    ahn = warp_sum(ahn);
    if (lane == 0) {
        float r = 1.f / (1.f + expf(-(air + bih[k] + ahr + bhh[k])));
        float z = 1.f / (1.f + expf(-(aiz + bih[k + HID] + ahz + bhh[k + HID])));
        float n = tanhf(ain + bih[k + 2 * HID] + r * (ahn + bhh[k + 2 * HID]));
        float hk = hidden[k];
        float hnew = (1.f - z) * n + z * hk;
        g_h[k] = hnew;
        dout[VOCAB + k] = hnew;  // h_new output
    }
}

// ---------------- K6: output projection GEMV (50257 x 1024) + LSE partials ----
__global__ void __launch_bounds__(256) k_outproj(const float* __restrict__ out_W,
                                                 const float* __restrict__ out_b,
                                                 float* __restrict__ dout) {
    __shared__ float4 sv[HID / 4];
    __shared__ float smem_m[8], smem_s[8];
    int t = threadIdx.x;
    const float4* gh = (const float4*)g_h;
    for (int i = t; i < HID / 4; i += 256) sv[i] = gh[i];
    __syncthreads();
    int wid = t >> 5, lane = t & 31;
    int gwarp = blockIdx.x * 8 + wid;
    float wm = BIG_NEG, ws = 0.f;
    const int stride = GEMV_BLOCKS * 8 * 4;
    for (int row0 = gwarp * 4; row0 < VOCAB; row0 += stride) {
        bool v1 = (row0 + 1) < VOCAB, v2 = (row0 + 2) < VOCAB, v3 = (row0 + 3) < VOCAB;
        const float4* r0 = (const float4*)(out_W + (size_t)row0 * HID);
        const float4* r1 = v1 ? (const float4*)(out_W + (size_t)(row0 + 1) * HID) : r0;
        const float4* r2 = v2 ? (const float4*)(out_W + (size_t)(row0 + 2) * HID) : r0;
        const float4* r3 = v3 ? (const float4*)(out_W + (size_t)(row0 + 3) * HID) : r0;
        float4 a0 = {0, 0, 0, 0}, a1 = a0, a2 = a0, a3 = a0;
#pragma unroll
        for (int i = 0; i < 8; i++) {
            int off = lane + 32 * i;
            float4 v = sv[off];
            float4 w0 = r0[off];
            float4 w1 = r1[off];
            float4 w2 = r2[off];
            float4 w3 = r3[off];
            a0.x += w0.x * v.x; a0.y += w0.y * v.y; a0.z += w0.z * v.z; a0.w += w0.w * v.w;
            a1.x += w1.x * v.x; a1.y += w1.y * v.y; a1.z += w1.z * v.z; a1.w += w1.w * v.w;
            a2.x += w2.x * v.x; a2.y += w2.y * v.y; a2.z += w2.z * v.z; a2.w += w2.w * v.w;
            a3.x += w3.x * v.x; a3.y += w3.y * v.y; a3.z += w3.z * v.z; a3.w += w3.w * v.w;
        }
        float l0 = warp_sum(a0.x + a0.y + a0.z + a0.w);
        float l1 = warp_sum(a1.x + a1.y + a1.z + a1.w);
        float l2 = warp_sum(a2.x + a2.y + a2.z + a2.w);
        float l3 = warp_sum(a3.x + a3.y + a3.z + a3.w);
        if (lane == 0) {
            l0 += out_b[row0];
            dout[row0] = l0;
            lse_update(wm, ws, l0);
            if (v1) { l1 += out_b[row0 + 1]; dout[row0 + 1] = l1; lse_update(wm, ws, l1); }
            if (v2) { l2 += out_b[row0 + 2]; dout[row0 + 2] = l2; lse_update(wm, ws, l2); }
            if (v3) { l3 += out_b[row0 + 3]; dout[row0 + 3] = l3; lse_update(wm, ws, l3); }
        }
    }
    if (lane == 0) { smem_m[wid] = wm; smem_s[wid] = ws; }
    __syncthreads();
    if (t == 0) {
        float m = BIG_NEG, s = 0.f;
#pragma unroll
        for (int i = 0; i < 8; i++) {
            float mi = smem_m[i], si = smem_s[i];
            float M = fmaxf(m, mi);
            s = s * expf(m - M) + si * expf(mi - M);
            m = M;
        }
        g_pm[blockIdx.x] = m;
        g_ps[blockIdx.x] = s;
    }
}

// ---------------- K7: combine partials -> log-sum-exp scalar ----------------
__global__ void k_lse() {
    __shared__ float sm[512], ss[512];
    int t = threadIdx.x;  // 512 threads
    float m = (t < GEMV_BLOCKS) ? g_pm[t] : BIG_NEG;
    float s = (t < GEMV_BLOCKS) ? g_ps[t] : 0.f;
    sm[t] = m;
    ss[t] = s;
    __syncthreads();
    for (int o = 256; o; o >>= 1) {
        if (t < o) {
            float m2 = sm[t + o], s2 = ss[t + o];
            float M = fmaxf(sm[t], m2);
            ss[t] = ss[t] * expf(sm[t] - M) + s2 * expf(m2 - M);
            sm[t] = M;
        }
        __syncthreads();
    }
    if (t == 0) g_lse = sm[0] + logf(ss[0]);
}

// ---------------- K8: logp = logit - lse (in place) ----------------
__global__ void k_sub(float* __restrict__ dout) {
    int i = blockIdx.x * blockDim.x + threadIdx.x;
    if (i < VOCAB) dout[i] -= g_lse;
}

// ---------------- launcher ----------------
extern "C" void kernel_launch(void* const* d_in, const int* in_sizes, int n_in,
                              void* d_out, int out_size) {
    const int*   inp    = (const int*)d_in[0];
    const float* hidden = (const float*)d_in[1];
    const float* enc    = (const float*)d_in[2];
    const float* emb    = (const float*)d_in[3];
    const float* attn_W = (const float*)d_in[4];
    const float* attn_b = (const float*)d_in[5];
    const float* comb_W = (const float*)d_in[6];
    const float* comb_b = (const float*)d_in[7];
    const float* Wih    = (const float*)d_in[8];
    const float* Whh    = (const float*)d_in[9];
    const float* bih    = (const float*)d_in[10];
    const float* bhh    = (const float*)d_in[11];
    const float* out_W  = (const float*)d_in[12];
    const float* out_b  = (const float*)d_in[13];
    float* out = (float*)d_out;

    k_attn_logits<<<64, 256>>>(inp, hidden, emb, attn_W, attn_b);
    k_softmax<<<1, 64>>>(out);
    k_applied<<<4, 256>>>(inp, emb, enc);
    k_combine<<<128, 256>>>(comb_W, comb_b);
    k_gru<<<128, 256>>>(Wih, Whh, bih, bhh, hidden, out);
    k_outproj<<<GEMV_BLOCKS, 256>>>(out_W, out_b, out);
    k_lse<<<1, 512>>>();
    k_sub<<<(VOCAB + 255) / 256, 256>>>(out);
}

// round 2
// speedup vs baseline: 1.1093x; 1.1093x over previous
#include <cuda_runtime.h>
#include <math.h>

#define VOCAB 50257
#define HID   1024
#define H2    2048
#define H3    3072
#define MAXLEN 64
#define GEMV_BLOCKS 592
#define BIG_NEG (-3.0e38f)

// ---------------- scratch ----------------
__device__ float g_logits[MAXLEN];
__device__ float g_cat[H2];       // [embedded, attn_applied]
__device__ float g_x[HID];        // relu(combine)
__device__ float g_gi[H3];        // Wih @ x + bih
__device__ float g_gh[H3];        // Whh @ h + bhh
__device__ float g_pm[GEMV_BLOCKS];
__device__ float g_ps[GEMV_BLOCKS];

__device__ __forceinline__ float warp_sum(float v) {
#pragma unroll
    for (int o = 16; o; o >>= 1) v += __shfl_xor_sync(0xffffffffu, v, o);
    return v;
}

__device__ __forceinline__ float dot4(float4 a, float4 b) {
    return a.x * b.x + a.y * b.y + a.z * b.z + a.w * b.w;
}

__device__ __forceinline__ void lse_update(float& m, float& s, float x) {
    float M = fmaxf(m, x);
    s = s * expf(m - M) + expf(x - M);
    m = M;
}

// ---------- K1: attn logits (blocks 0..63) + Whh gates (blocks 64..447) ----------
__global__ void __launch_bounds__(256) k_pre(const int* __restrict__ inp,
                                             const float* __restrict__ hidden,
                                             const float* __restrict__ emb,
                                             const float* __restrict__ attn_W,
                                             const float* __restrict__ attn_b,
                                             const float* __restrict__ Whh,
                                             const float* __restrict__ bhh) {
    int t = threadIdx.x;
    if (blockIdx.x < 64) {
        // attention logit row: dot(attn_W[row], [emb_row ; hidden]) over 2048
        int row = blockIdx.x;
        const float* er = emb + (size_t)inp[0] * HID;
        const float* wr = attn_W + (size_t)row * H2;
        float acc = 0.f;
        for (int j = t; j < H2; j += 256) {
            float v = (j < HID) ? er[j] : hidden[j - HID];
            acc += wr[j] * v;
        }
        acc = warp_sum(acc);
        __shared__ float s[8];
        if ((t & 31) == 0) s[t >> 5] = acc;
        __syncthreads();
        if (t == 0) {
            float a = 0.f;
#pragma unroll
            for (int i = 0; i < 8; i++) a += s[i];
            g_logits[row] = a + attn_b[row];
        }
    } else {
        // Whh gate row GEMV: one warp per row, 3072 rows total
        __shared__ float4 sh[HID / 4];
        const float4* h4 = (const float4*)hidden;
        for (int i = t; i < HID / 4; i += 256) sh[i] = h4[i];
        __syncthreads();
        int wid = t >> 5, lane = t & 31;
        int row = (blockIdx.x - 64) * 8 + wid;  // 0..3071
        const float4* wr = (const float4*)(Whh + (size_t)row * HID);
        float acc = 0.f;
#pragma unroll
        for (int i = 0; i < 8; i++) acc += dot4(wr[lane + 32 * i], sh[lane + 32 * i]);
        acc = warp_sum(acc);
        if (lane == 0) g_gh[row] = acc + bhh[row];
    }
}

// ---------- K2: softmax (redundant per block) + attn_applied + cat ----------
__global__ void __launch_bounds__(256) k_applied(const int* __restrict__ inp,
                                                 const float* __restrict__ emb,
                                                 const float* __restrict__ enc,
                                                 float* __restrict__ dout) {
    int t = threadIdx.x;
    __shared__ float sw[MAXLEN];
    // redundant 64-wide softmax in every block (reads 256B from L2)
    if (t < MAXLEN) sw[t] = g_logits[t];
    __syncthreads();
    if (t < 32) {
        float a = sw[t], b = sw[t + 32];
        float m = fmaxf(a, b);
#pragma unroll
        for (int o = 16; o; o >>= 1) m = fmaxf(m, __shfl_xor_sync(0xffffffffu, m, o));
        float e0 = expf(a - m), e1 = expf(b - m);
        float s = e0 + e1;
#pragma unroll
        for (int o = 16; o; o >>= 1) s += __shfl_xor_sync(0xffffffffu, s, o);
        sw[t] = e0 / s;
        sw[t + 32] = e1 / s;
        if (blockIdx.x == 0) {
            dout[VOCAB + HID + t] = sw[t];
            dout[VOCAB + HID + t + 32] = sw[t + 32];
        }
    }
    __syncthreads();
    int j = blockIdx.x * 256 + t;  // 0..1023
    float a = 0.f;
#pragma unroll 8
    for (int i = 0; i < MAXLEN; i++) a += sw[i] * enc[i * HID + j];
    g_cat[HID + j] = a;
    g_cat[j] = emb[(size_t)inp[0] * HID + j];
}

// ---------- K3: combine GEMV + relu (1024 x 2048), split-K=2, 256 blocks ----------
__global__ void __launch_bounds__(256) k_combine(const float* __restrict__ comb_W,
                                                 const float* __restrict__ comb_b) {
    __shared__ float4 sc[H2 / 4];
    __shared__ float sred[8];
    int t = threadIdx.x;
    const float4* gc = (const float4*)g_cat;
    for (int i = t; i < H2 / 4; i += 256) sc[i] = gc[i];
    __syncthreads();
    int wid = t >> 5, lane = t & 31;
    int row = blockIdx.x * 4 + (wid >> 1);   // 4 rows per block
    int half = wid & 1;                       // which 1024-elem half
    const float4* wr = (const float4*)(comb_W + (size_t)row * H2) + half * 256;
    const float4* vr = sc + half * 256;
    float acc = 0.f;
#pragma unroll
    for (int i = 0; i < 8; i++) acc += dot4(wr[lane + 32 * i], vr[lane + 32 * i]);
    acc = warp_sum(acc);
    if (lane == 0) sred[wid] = acc;
    __syncthreads();
    if (t < 4) {
        int r = blockIdx.x * 4 + t;
        g_x[r] = fmaxf(sred[2 * t] + sred[2 * t + 1] + comb_b[r], 0.f);
    }
}

// ---------- K4: gi = Wih @ x + bih (3072 rows, warp per row, 384 blocks) ----------
__global__ void __launch_bounds__(256) k_gih(const float* __restrict__ Wih,
                                             const float* __restrict__ bih) {
    __shared__ float4 sx[HID / 4];
    int t = threadIdx.x;
    const float4* gx = (const float4*)g_x;
    for (int i = t; i < HID / 4; i += 256) sx[i] = gx[i];
    __syncthreads();
    int wid = t >> 5, lane = t & 31;
    int row = blockIdx.x * 8 + wid;
    const float4* wr = (const float4*)(Wih + (size_t)row * HID);
    float acc = 0.f;
#pragma unroll
    for (int i = 0; i < 8; i++) acc += dot4(wr[lane + 32 * i], sx[lane + 32 * i]);
    acc = warp_sum(acc);
    if (lane == 0) g_gi[row] = acc + bih[row];
}

// ---------- K5: h_new (redundant per block) + big GEMV + LSE partials ----------
__global__ void __launch_bounds__(256) k_outproj(const float* __restrict__ hidden,
                                                 const float* __restrict__ out_W,
                                                 const float* __restrict__ out_b,
                                                 float* __restrict__ dout) {
    __shared__ float sv[HID];
    __shared__ float smem_m[8], smem_s[8];
    int t = threadIdx.x;
    // recompute h_new redundantly (reads 24KB gi/gh from L2)
    for (int k = t; k < HID; k += 256) {
        float r = 1.f / (1.f + expf(-(g_gi[k] + g_gh[k])));
        float z = 1.f / (1.f + expf(-(g_gi[k + HID] + g_gh[k + HID])));
        float n = tanhf(g_gi[k + 2 * HID] + r * g_gh[k + 2 * HID]);
        float hnew = (1.f - z) * n + z * hidden[k];
        sv[k] = hnew;
        if (blockIdx.x == 0) dout[VOCAB + k] = hnew;
    }
    __syncthreads();
    const float4* sv4 = (const float4*)sv;
    int wid = t >> 5, lane = t & 31;
    int gwarp = blockIdx.x * 8 + wid;
    float wm = BIG_NEG, ws = 0.f;
    const int stride = GEMV_BLOCKS * 8 * 4;
    for (int row0 = gwarp * 4; row0 < VOCAB; row0 += stride) {
        bool v1 = (row0 + 1) < VOCAB, v2 = (row0 + 2) < VOCAB, v3 = (row0 + 3) < VOCAB;
        const float4* r0 = (const float4*)(out_W + (size_t)row0 * HID);
        const float4* r1 = v1 ? (const float4*)(out_W + (size_t)(row0 + 1) * HID) : r0;
        const float4* r2 = v2 ? (const float4*)(out_W + (size_t)(row0 + 2) * HID) : r0;
        const float4* r3 = v3 ? (const float4*)(out_W + (size_t)(row0 + 3) * HID) : r0;
        float a0 = 0.f, a1 = 0.f, a2 = 0.f, a3 = 0.f;
#pragma unroll
        for (int i = 0; i < 8; i++) {
            int off = lane + 32 * i;
            float4 v = sv4[off];
            a0 += dot4(r0[off], v);
            a1 += dot4(r1[off], v);
            a2 += dot4(r2[off], v);
            a3 += dot4(r3[off], v);
        }
        a0 = warp_sum(a0);
        a1 = warp_sum(a1);
        a2 = warp_sum(a2);
        a3 = warp_sum(a3);
        if (lane == 0) {
            a0 += out_b[row0];
            dout[row0] = a0;
            lse_update(wm, ws, a0);
            if (v1) { a1 += out_b[row0 + 1]; dout[row0 + 1] = a1; lse_update(wm, ws, a1); }
            if (v2) { a2 += out_b[row0 + 2]; dout[row0 + 2] = a2; lse_update(wm, ws, a2); }
            if (v3) { a3 += out_b[row0 + 3]; dout[row0 + 3] = a3; lse_update(wm, ws, a3); }
        }
    }
    if (lane == 0) { smem_m[wid] = wm; smem_s[wid] = ws; }
    __syncthreads();
    if (t == 0) {
        float m = BIG_NEG, s = 0.f;
#pragma unroll
        for (int i = 0; i < 8; i++) {
            float mi = smem_m[i], si = smem_s[i];
            float M = fmaxf(m, mi);
            s = s * expf(m - M) + si * expf(mi - M);
            m = M;
        }
        g_pm[blockIdx.x] = m;
        g_ps[blockIdx.x] = s;
    }
}

// ---------- K6: redundant LSE combine + subtract ----------
__global__ void __launch_bounds__(256) k_final(float* __restrict__ dout) {
    __shared__ float sm[256], ss[256];
    int t = threadIdx.x;
    float m = BIG_NEG, s = 0.f;
    for (int i = t; i < GEMV_BLOCKS; i += 256) {
        float mi = g_pm[i], si = g_ps[i];
        float M = fmaxf(m, mi);
        s = s * expf(m - M) + si * expf(mi - M);
        m = M;
    }
    sm[t] = m;
    ss[t] = s;
    __syncthreads();
    for (int o = 128; o; o >>= 1) {
        if (t < o) {
            float m2 = sm[t + o], s2 = ss[t + o];
            float M = fmaxf(sm[t], m2);
            ss[t] = ss[t] * expf(sm[t] - M) + s2 * expf(m2 - M);
            sm[t] = M;
        }
        __syncthreads();
    }
    float lse = sm[0] + logf(ss[0]);
    int i = blockIdx.x * 256 + t;
    if (i < VOCAB) dout[i] -= lse;
}

// ---------------- launcher ----------------
extern "C" void kernel_launch(void* const* d_in, const int* in_sizes, int n_in,
                              void* d_out, int out_size) {
    const int*   inp    = (const int*)d_in[0];
    const float* hidden = (const float*)d_in[1];
    const float* enc    = (const float*)d_in[2];
    const float* emb    = (const float*)d_in[3];
    const float* attn_W = (const float*)d_in[4];
    const float* attn_b = (const float*)d_in[5];
    const float* comb_W = (const float*)d_in[6];
    const float* comb_b = (const float*)d_in[7];
    const float* Wih    = (const float*)d_in[8];
    const float* Whh    = (const float*)d_in[9];
    const float* bih    = (const float*)d_in[10];
    const float* bhh    = (const float*)d_in[11];
    const float* out_W  = (const float*)d_in[12];
    const float* out_b  = (const float*)d_in[13];
    float* out = (float*)d_out;

    k_pre<<<64 + 384, 256>>>(inp, hidden, emb, attn_W, attn_b, Whh, bhh);
    k_applied<<<4, 256>>>(inp, emb, enc, out);
    k_combine<<<256, 256>>>(comb_W, comb_b);
    k_gih<<<384, 256>>>(Wih, bih);
    k_outproj<<<GEMV_BLOCKS, 256>>>(hidden, out_W, out_b, out);
    k_final<<<(VOCAB + 255) / 256, 256>>>(out);
}

// round 3
// speedup vs baseline: 1.1289x; 1.0176x over previous
#include <cuda_runtime.h>
#include <math.h>

#define VOCAB 50257
#define HID   1024
#define H2    2048
#define H3    3072
#define MAXLEN 64
#define OUT_ROWS_PER_WARP 8
#define GEMV_BLOCKS 786   // ceil(50257 / (8 warps * 8 rows))
#define BIG_NEG (-3.0e38f)

// ---------------- scratch ----------------
__device__ float g_logits[MAXLEN];
__device__ float g_cat[H2];       // [embedded, attn_applied]
__device__ float g_x[HID];        // relu(combine)
__device__ float g_gi[H3];        // Wih @ x + bih
__device__ float g_gh[H3];        // Whh @ h + bhh
__device__ float g_pm[GEMV_BLOCKS];
__device__ float g_ps[GEMV_BLOCKS];

__device__ __forceinline__ float warp_sum(float v) {
#pragma unroll
    for (int o = 16; o; o >>= 1) v += __shfl_xor_sync(0xffffffffu, v, o);
    return v;
}

__device__ __forceinline__ float dot4(float4 a, float4 b) {
    return a.x * b.x + a.y * b.y + a.z * b.z + a.w * b.w;
}

__device__ __forceinline__ void lse_update(float& m, float& s, float x) {
    float M = fmaxf(m, x);
    s = s * expf(m - M) + expf(x - M);
    m = M;
}

// ---------- K1: attn logits (blocks 0..63) + Whh gates (blocks 64..255) ----------
__global__ void __launch_bounds__(256) k_pre(const int* __restrict__ inp,
                                             const float* __restrict__ hidden,
                                             const float* __restrict__ emb,
                                             const float* __restrict__ attn_W,
                                             const float* __restrict__ attn_b,
                                             const float* __restrict__ Whh,
                                             const float* __restrict__ bhh) {
    int t = threadIdx.x;
    if (blockIdx.x < 64) {
        int row = blockIdx.x;
        const float* er = emb + (size_t)inp[0] * HID;
        const float* wr = attn_W + (size_t)row * H2;
        float acc = 0.f;
        for (int j = t; j < H2; j += 256) {
            float v = (j < HID) ? er[j] : hidden[j - HID];
            acc += wr[j] * v;
        }
        acc = warp_sum(acc);
        __shared__ float s[8];
        if ((t & 31) == 0) s[t >> 5] = acc;
        __syncthreads();
        if (t == 0) {
            float a = 0.f;
#pragma unroll
            for (int i = 0; i < 8; i++) a += s[i];
            g_logits[row] = a + attn_b[row];
        }
    } else {
        // Whh gate GEMV: 2 rows per warp, 192 blocks x 8 warps x 2 = 3072 rows
        __shared__ float4 sh[HID / 4];
        const float4* h4 = (const float4*)hidden;
        for (int i = t; i < HID / 4; i += 256) sh[i] = h4[i];
        __syncthreads();
        int wid = t >> 5, lane = t & 31;
        int row = ((blockIdx.x - 64) * 8 + wid) * 2;
        const float4* w0 = (const float4*)(Whh + (size_t)row * HID);
        const float4* w1 = (const float4*)(Whh + (size_t)(row + 1) * HID);
        float a0 = 0.f, a1 = 0.f;
#pragma unroll
        for (int i = 0; i < 8; i++) {
            int off = lane + 32 * i;
            float4 v = sh[off];
            a0 += dot4(w0[off], v);
            a1 += dot4(w1[off], v);
        }
        a0 = warp_sum(a0);
        a1 = warp_sum(a1);
        if (lane == 0) {
            g_gh[row] = a0 + bhh[row];
            g_gh[row + 1] = a1 + bhh[row + 1];
        }
    }
}

// ---------- K2: softmax (redundant per block) + attn_applied + cat ----------
__global__ void __launch_bounds__(256) k_applied(const int* __restrict__ inp,
                                                 const float* __restrict__ emb,
                                                 const float* __restrict__ enc,
                                                 float* __restrict__ dout) {
    int t = threadIdx.x;
    __shared__ float sw[MAXLEN];
    if (t < MAXLEN) sw[t] = g_logits[t];
    __syncthreads();
    if (t < 32) {
        float a = sw[t], b = sw[t + 32];
        float m = fmaxf(a, b);
#pragma unroll
        for (int o = 16; o; o >>= 1) m = fmaxf(m, __shfl_xor_sync(0xffffffffu, m, o));
        float e0 = expf(a - m), e1 = expf(b - m);
        float s = e0 + e1;
#pragma unroll
        for (int o = 16; o; o >>= 1) s += __shfl_xor_sync(0xffffffffu, s, o);
        sw[t] = e0 / s;
        sw[t + 32] = e1 / s;
        if (blockIdx.x == 0) {
            dout[VOCAB + HID + t] = sw[t];
            dout[VOCAB + HID + t + 32] = sw[t + 32];
        }
    }
    __syncthreads();
    int j = blockIdx.x * 256 + t;  // 0..1023
    float a = 0.f;
#pragma unroll 8
    for (int i = 0; i < MAXLEN; i++) a += sw[i] * enc[i * HID + j];
    g_cat[HID + j] = a;
    g_cat[j] = emb[(size_t)inp[0] * HID + j];
}

// ---------- K3: combine GEMV + relu (1024 x 2048), split-K=2, 256 blocks ----------
__global__ void __launch_bounds__(256) k_combine(const float* __restrict__ comb_W,
                                                 const float* __restrict__ comb_b) {
    __shared__ float4 sc[H2 / 4];
    __shared__ float sred[8];
    int t = threadIdx.x;
    const float4* gc = (const float4*)g_cat;
    for (int i = t; i < H2 / 4; i += 256) sc[i] = gc[i];
    __syncthreads();
    int wid = t >> 5, lane = t & 31;
    int row = blockIdx.x * 4 + (wid >> 1);
    int half = wid & 1;
    const float4* wr = (const float4*)(comb_W + (size_t)row * H2) + half * 256;
    const float4* vr = sc + half * 256;
    float acc = 0.f;
#pragma unroll
    for (int i = 0; i < 8; i++) acc += dot4(wr[lane + 32 * i], vr[lane + 32 * i]);
    acc = warp_sum(acc);
    if (lane == 0) sred[wid] = acc;
    __syncthreads();
    if (t < 4) {
        int r = blockIdx.x * 4 + t;
        g_x[r] = fmaxf(sred[2 * t] + sred[2 * t + 1] + comb_b[r], 0.f);
    }
}

// ---------- K4: gi = Wih @ x + bih (3072 rows, 2 rows/warp, 192 blocks) ----------
__global__ void __launch_bounds__(256) k_gih(const float* __restrict__ Wih,
                                             const float* __restrict__ bih) {
    __shared__ float4 sx[HID / 4];
    int t = threadIdx.x;
    const float4* gx = (const float4*)g_x;
    for (int i = t; i < HID / 4; i += 256) sx[i] = gx[i];
    __syncthreads();
    int wid = t >> 5, lane = t & 31;
    int row = (blockIdx.x * 8 + wid) * 2;
    const float4* w0 = (const float4*)(Wih + (size_t)row * HID);
    const float4* w1 = (const float4*)(Wih + (size_t)(row + 1) * HID);
    float a0 = 0.f, a1 = 0.f;
#pragma unroll
    for (int i = 0; i < 8; i++) {
        int off = lane + 32 * i;
        float4 v = sx[off];
        a0 += dot4(w0[off], v);
        a1 += dot4(w1[off], v);
    }
    a0 = warp_sum(a0);
    a1 = warp_sum(a1);
    if (lane == 0) {
        g_gi[row] = a0 + bih[row];
        g_gi[row + 1] = a1 + bih[row + 1];
    }
}

// ---------- K5: h_new (redundant) + single-pass big GEMV (8 rows/warp) ----------
__global__ void __launch_bounds__(256) k_outproj(const float* __restrict__ hidden,
                                                 const float* __restrict__ out_W,
                                                 const float* __restrict__ out_b,
                                                 float* __restrict__ dout) {
    __shared__ float sv[HID];
    __shared__ float smem_m[8], smem_s[8];
    int t = threadIdx.x;
    for (int k = t; k < HID; k += 256) {
        float r = 1.f / (1.f + expf(-(g_gi[k] + g_gh[k])));
        float z = 1.f / (1.f + expf(-(g_gi[k + HID] + g_gh[k + HID])));
        float n = tanhf(g_gi[k + 2 * HID] + r * g_gh[k + 2 * HID]);
        float hnew = (1.f - z) * n + z * hidden[k];
        sv[k] = hnew;
        if (blockIdx.x == 0) dout[VOCAB + k] = hnew;
    }
    __syncthreads();
    const float4* sv4 = (const float4*)sv;
    int wid = t >> 5, lane = t & 31;
    int gwarp = blockIdx.x * 8 + wid;
    int row0 = gwarp * OUT_ROWS_PER_WARP;

    // clamp row pointers for the tail (results discarded for invalid rows)
    const float4* rp[OUT_ROWS_PER_WARP];
#pragma unroll
    for (int r = 0; r < OUT_ROWS_PER_WARP; r++) {
        int row = row0 + r;
        if (row >= VOCAB) row = VOCAB - 1;
        rp[r] = (const float4*)(out_W + (size_t)row * HID);
    }
    float acc[OUT_ROWS_PER_WARP];
#pragma unroll
    for (int r = 0; r < OUT_ROWS_PER_WARP; r++) acc[r] = 0.f;
#pragma unroll
    for (int i = 0; i < 8; i++) {
        int off = lane + 32 * i;
        float4 v = sv4[off];
#pragma unroll
        for (int r = 0; r < OUT_ROWS_PER_WARP; r++) acc[r] += dot4(rp[r][off], v);
    }
#pragma unroll
    for (int r = 0; r < OUT_ROWS_PER_WARP; r++) acc[r] = warp_sum(acc[r]);

    float wm = BIG_NEG, ws = 0.f;
    if (lane == 0) {
#pragma unroll
        for (int r = 0; r < OUT_ROWS_PER_WARP; r++) {
            int row = row0 + r;
            if (row < VOCAB) {
                float l = acc[r] + out_b[row];
                dout[row] = l;
                lse_update(wm, ws, l);
            }
        }
        smem_m[wid] = wm;
        smem_s[wid] = ws;
    }
    __syncthreads();
    if (t == 0) {
        float m = BIG_NEG, s = 0.f;
#pragma unroll
        for (int i = 0; i < 8; i++) {
            float mi = smem_m[i], si = smem_s[i];
            float M = fmaxf(m, mi);
            s = s * expf(m - M) + si * expf(mi - M);
            m = M;
        }
        g_pm[blockIdx.x] = m;
        g_ps[blockIdx.x] = s;
    }
}

// ---------- K6: redundant LSE combine + subtract ----------
__global__ void __launch_bounds__(256) k_final(float* __restrict__ dout) {
    __shared__ float sm[256], ss[256];
    int t = threadIdx.x;
    float m = BIG_NEG, s = 0.f;
    for (int i = t; i < GEMV_BLOCKS; i += 256) {
        float mi = g_pm[i], si = g_ps[i];
        float M = fmaxf(m, mi);
        s = s * expf(m - M) + si * expf(mi - M);
        m = M;
    }
    sm[t] = m;
    ss[t] = s;
    __syncthreads();
    for (int o = 128; o; o >>= 1) {
        if (t < o) {
            float m2 = sm[t + o], s2 = ss[t + o];
            float M = fmaxf(sm[t], m2);
            ss[t] = ss[t] * expf(sm[t] - M) + s2 * expf(m2 - M);
            sm[t] = M;
        }
        __syncthreads();
    }
    float lse = sm[0] + logf(ss[0]);
    int i = blockIdx.x * 256 + t;
    if (i < VOCAB) dout[i] -= lse;
}

// ---------------- launcher ----------------
extern "C" void kernel_launch(void* const* d_in, const int* in_sizes, int n_in,
                              void* d_out, int out_size) {
    const int*   inp    = (const int*)d_in[0];
    const float* hidden = (const float*)d_in[1];
    const float* enc    = (const float*)d_in[2];
    const float* emb    = (const float*)d_in[3];
    const float* attn_W = (const float*)d_in[4];
    const float* attn_b = (const float*)d_in[5];
    const float* comb_W = (const float*)d_in[6];
    const float* comb_b = (const float*)d_in[7];
    const float* Wih    = (const float*)d_in[8];
    const float* Whh    = (const float*)d_in[9];
    const float* bih    = (const float*)d_in[10];
    const float* bhh    = (const float*)d_in[11];
    const float* out_W  = (const float*)d_in[12];
    const float* out_b  = (const float*)d_in[13];
    float* out = (float*)d_out;

    k_pre<<<64 + 192, 256>>>(inp, hidden, emb, attn_W, attn_b, Whh, bhh);
    k_applied<<<4, 256>>>(inp, emb, enc, out);
    k_combine<<<256, 256>>>(comb_W, comb_b);
    k_gih<<<192, 256>>>(Wih, bih);
    k_outproj<<<GEMV_BLOCKS, 256>>>(hidden, out_W, out_b, out);
    k_final<<<(VOCAB + 255) / 256, 256>>>(out);
}

// round 4
// speedup vs baseline: 1.2795x; 1.1334x over previous
#include <cuda_runtime.h>
#include <math.h>

#define VOCAB 50257
#define HID   1024
#define H2    2048
#define H3    3072
#define MAXLEN 64
#define GRID 148
#define NT 512
#define NW (GRID * 16)          // total warps = 2368
#define NGROUPS 6283            // ceil(VOCAB / 8)
#define BIG_NEG (-3.0e38f)

// ---------------- scratch ----------------
__device__ unsigned g_cnt;      // barrier arrival counter (self-resetting)
__device__ unsigned g_gen;      // barrier generation (monotone across replays)
__device__ float g_logits[MAXLEN];
__device__ float g_cat[H2];
__device__ float g_x[HID];
__device__ float g_gi[H3];
__device__ float g_gh[H3];
__device__ float g_pm[GRID];
__device__ float g_ps[GRID];

__device__ __forceinline__ float warp_sum(float v) {
#pragma unroll
    for (int o = 16; o; o >>= 1) v += __shfl_xor_sync(0xffffffffu, v, o);
    return v;
}

__device__ __forceinline__ float dot4(float4 a, float4 b) {
    return a.x * b.x + a.y * b.y + a.z * b.z + a.w * b.w;
}

__device__ __forceinline__ void lse_update(float& m, float& s, float x) {
    float M = fmaxf(m, x);
    s = s * expf(m - M) + expf(x - M);
    m = M;
}

// merge (m2,s2) into (m,s)
__device__ __forceinline__ void lse_merge(float& m, float& s, float m2, float s2) {
    float M = fmaxf(m, m2);
    s = s * expf(m - M) + s2 * expf(m2 - M);
    m = M;
}

// sense-reversing grid barrier; safe because grid (148) <= #SMs -> all CTAs resident
__device__ __forceinline__ void gsync() {
    __syncthreads();
    if (threadIdx.x == 0) {
        __threadfence();
        unsigned my = *(volatile unsigned*)&g_gen;
        unsigned old = atomicAdd(&g_cnt, 1u);
        if (old == GRID - 1) {
            g_cnt = 0;
            __threadfence();
            atomicAdd(&g_gen, 1u);
        } else {
            while (*(volatile unsigned*)&g_gen == my) { }
        }
        __threadfence();
    }
    __syncthreads();
}

__global__ void __launch_bounds__(NT, 1) k_fused(
    const int* __restrict__ inp,
    const float* __restrict__ hidden,
    const float* __restrict__ enc,
    const float* __restrict__ emb,
    const float* __restrict__ attn_W,
    const float* __restrict__ attn_b,
    const float* __restrict__ comb_W,
    const float* __restrict__ comb_b,
    const float* __restrict__ Wih,
    const float* __restrict__ Whh,
    const float* __restrict__ bih,
    const float* __restrict__ bhh,
    const float* __restrict__ out_W,
    const float* __restrict__ out_b,
    float* __restrict__ dout)
{
    __shared__ float sw[MAXLEN];
    __shared__ float sv[HID];
    __shared__ float rm[16], rs[16];
    __shared__ float sm[NT], ss[NT];

    const int t = threadIdx.x;
    const int b = blockIdx.x;
    const int wid = t >> 5, lane = t & 31;
    const int GW = b * 16 + wid;

    const float4* h4 = (const float4*)hidden;

    // ======== Phase 0: attn logits (warps 0..63) || Whh gates (rest) ========
    if (GW < 64) {
        const int row = GW;
        const float4* er4 = (const float4*)(emb + (size_t)inp[0] * HID);
        const float4* wr = (const float4*)(attn_W + (size_t)row * H2);
        float acc = 0.f;
#pragma unroll
        for (int i = 0; i < 16; i++) {
            int off = lane + 32 * i;
            float4 v = (i < 8) ? er4[off] : h4[off - 256];
            acc += dot4(wr[off], v);
        }
        acc = warp_sum(acc);
        if (lane == 0) g_logits[row] = acc + attn_b[row];
    } else {
        for (int r = GW - 64; r < H3; r += NW - 64) {
            const float4* wr = (const float4*)(Whh + (size_t)r * HID);
            float acc = 0.f;
#pragma unroll
            for (int i = 0; i < 8; i++) {
                int off = lane + 32 * i;
                acc += dot4(wr[off], h4[off]);
            }
            acc = warp_sum(acc);
            if (lane == 0) g_gh[r] = acc + bhh[r];
        }
    }
    gsync();

    // ======== Phase 1: softmax + attn_applied + cat (blocks 0,1) ========
    if (b < 2) {
        if (t < MAXLEN) sw[t] = g_logits[t];
        __syncthreads();
        if (t < 32) {
            float a = sw[t], c = sw[t + 32];
            float m = fmaxf(a, c);
#pragma unroll
            for (int o = 16; o; o >>= 1) m = fmaxf(m, __shfl_xor_sync(0xffffffffu, m, o));
            float e0 = expf(a - m), e1 = expf(c - m);
            float s = e0 + e1;
#pragma unroll
            for (int o = 16; o; o >>= 1) s += __shfl_xor_sync(0xffffffffu, s, o);
            sw[t] = e0 / s;
            sw[t + 32] = e1 / s;
            if (b == 0) {
                dout[VOCAB + HID + t] = sw[t];
                dout[VOCAB + HID + t + 32] = sw[t + 32];
            }
        }
        __syncthreads();
        int j = b * NT + t;   // 0..1023
        float a = 0.f;
#pragma unroll 8
        for (int i = 0; i < MAXLEN; i++) a += sw[i] * enc[i * HID + j];
        g_cat[HID + j] = a;
        g_cat[j] = emb[(size_t)inp[0] * HID + j];
    }
    gsync();

    // ======== Phase 2: combine GEMV + relu (1024 rows x 2048) ========
    if (GW < HID) {
        const float4* wr = (const float4*)(comb_W + (size_t)GW * H2);
        const float4* c4 = (const float4*)g_cat;
        float acc = 0.f;
#pragma unroll
        for (int i = 0; i < 16; i++) {
            int off = lane + 32 * i;
            acc += dot4(wr[off], c4[off]);
        }
        acc = warp_sum(acc);
        if (lane == 0) g_x[GW] = fmaxf(acc + comb_b[GW], 0.f);
    }
    gsync();

    // ======== Phase 3: gi = Wih @ x + bih (3072 rows) ========
    {
        const float4* x4 = (const float4*)g_x;
        for (int r = GW; r < H3; r += NW) {
            const float4* wr = (const float4*)(Wih + (size_t)r * HID);
            float acc = 0.f;
#pragma unroll
            for (int i = 0; i < 8; i++) {
                int off = lane + 32 * i;
                acc += dot4(wr[off], x4[off]);
            }
            acc = warp_sum(acc);
            if (lane == 0) g_gi[r] = acc + bih[r];
        }
    }
    gsync();

    // ======== Phase 4: h_new (redundant per block) + out-proj GEMV + LSE ========
    for (int k = t; k < HID; k += NT) {
        float r = 1.f / (1.f + expf(-(g_gi[k] + g_gh[k])));
        float z = 1.f / (1.f + expf(-(g_gi[k + HID] + g_gh[k + HID])));
        float n = tanhf(g_gi[k + 2 * HID] + r * g_gh[k + 2 * HID]);
        float hnew = (1.f - z) * n + z * hidden[k];
        sv[k] = hnew;
        if (b == 0) dout[VOCAB + k] = hnew;
    }
    __syncthreads();
    {
        const float4* sv4 = (const float4*)sv;
        float wm = BIG_NEG, ws = 0.f;
        for (int g = GW; g < NGROUPS; g += NW) {
            int row0 = g * 8;
            const float4* rp[8];
#pragma unroll
            for (int r = 0; r < 8; r++) {
                int row = row0 + r;
                if (row >= VOCAB) row = VOCAB - 1;
                rp[r] = (const float4*)(out_W + (size_t)row * HID);
            }
            float acc[8];
#pragma unroll
            for (int r = 0; r < 8; r++) acc[r] = 0.f;
#pragma unroll
            for (int i = 0; i < 8; i++) {
                int off = lane + 32 * i;
                float4 v = sv4[off];
#pragma unroll
                for (int r = 0; r < 8; r++) acc[r] += dot4(rp[r][off], v);
            }
#pragma unroll
            for (int r = 0; r < 8; r++) acc[r] = warp_sum(acc[r]);
            if (lane == 0) {
#pragma unroll
                for (int r = 0; r < 8; r++) {
                    int row = row0 + r;
                    if (row < VOCAB) {
                        float l = acc[r] + out_b[row];
                        dout[row] = l;
                        lse_update(wm, ws, l);
                    }
                }
            }
        }
        if (lane == 0) { rm[wid] = wm; rs[wid] = ws; }
    }
    __syncthreads();
    if (t == 0) {
        float m = BIG_NEG, s = 0.f;
#pragma unroll
        for (int i = 0; i < 16; i++) lse_merge(m, s, rm[i], rs[i]);
        g_pm[b] = m;
        g_ps[b] = s;
    }
    gsync();

    // ======== Phase 5: LSE merge (redundant per block) + subtract ========
    {
        float m = BIG_NEG, s = 0.f;
        for (int i = t; i < GRID; i += NT) lse_merge(m, s, g_pm[i], g_ps[i]);
        sm[t] = m;
        ss[t] = s;
        __syncthreads();
        for (int o = NT / 2; o; o >>= 1) {
            if (t < o) lse_merge(sm[t], ss[t], sm[t + o], ss[t + o]);
            __syncthreads();
        }
        float lse = sm[0] + logf(ss[0]);
        for (int i = b * NT + t; i < VOCAB; i += GRID * NT) dout[i] -= lse;
    }
}

// ---------------- launcher ----------------
extern "C" void kernel_launch(void* const* d_in, const int* in_sizes, int n_in,
                              void* d_out, int out_size) {
    const int*   inp    = (const int*)d_in[0];
    const float* hidden = (const float*)d_in[1];
    const float* enc    = (const float*)d_in[2];
    const float* emb    = (const float*)d_in[3];
    const float* attn_W = (const float*)d_in[4];
    const float* attn_b = (const float*)d_in[5];
    const float* comb_W = (const float*)d_in[6];
    const float* comb_b = (const float*)d_in[7];
    const float* Wih    = (const float*)d_in[8];
    const float* Whh    = (const float*)d_in[9];
    const float* bih    = (const float*)d_in[10];
    const float* bhh    = (const float*)d_in[11];
    const float* out_W  = (const float*)d_in[12];
    const float* out_b  = (const float*)d_in[13];
    float* out = (float*)d_out;

    k_fused<<<GRID, NT>>>(inp, hidden, enc, emb, attn_W, attn_b,
                          comb_W, comb_b, Wih, Whh, bih, bhh,
                          out_W, out_b, out);
}

// round 5
// speedup vs baseline: 1.3199x; 1.0316x over previous
#include <cuda_runtime.h>
#include <math.h>

#define VOCAB 50257
#define HID   1024
#define H2    2048
#define H3    3072
#define MAXLEN 64
#define GRID 148
#define NT 512
#define NW (GRID * 16)          // 2368 warps
#define NGROUPS 6283            // ceil(VOCAB / 8)
#define BIG_NEG (-3.0e38f)

// ---------------- scratch ----------------
__device__ unsigned g_cnt;
__device__ unsigned g_gen;
__device__ unsigned g_work;
__device__ float g_logits[MAXLEN];
__device__ float g_cat[H2];
__device__ float g_xp[H2];      // combine split-K partials: [k] and [k+1024]
__device__ float g_gi[H3];
__device__ float g_gh[H3];
__device__ float g_pm[GRID];
__device__ float g_ps[GRID];

__device__ __forceinline__ float warp_sum(float v) {
#pragma unroll
    for (int o = 16; o; o >>= 1) v += __shfl_xor_sync(0xffffffffu, v, o);
    return v;
}

__device__ __forceinline__ float dot4(float4 a, float4 b) {
    return a.x * b.x + a.y * b.y + a.z * b.z + a.w * b.w;
}

__device__ __forceinline__ void lse_update(float& m, float& s, float x) {
    float M = fmaxf(m, x);
    s = s * __expf(m - M) + __expf(x - M);
    m = M;
}

__device__ __forceinline__ void lse_merge(float& m, float& s, float m2, float s2) {
    float M = fmaxf(m, m2);
    s = s * __expf(m - M) + s2 * __expf(m2 - M);
    m = M;
}

// grid barrier; safe: GRID (148) <= #SMs so all CTAs co-resident
__device__ __forceinline__ void gsync() {
    __syncthreads();
    if (threadIdx.x == 0) {
        __threadfence();
        unsigned my = *(volatile unsigned*)&g_gen;
        unsigned old = atomicAdd(&g_cnt, 1u);
        if (old == GRID - 1) {
            g_cnt = 0;
            __threadfence();
            atomicAdd(&g_gen, 1u);
        } else {
            while (*(volatile unsigned*)&g_gen == my) { }
        }
        __threadfence();
    }
    __syncthreads();
}

__global__ void __launch_bounds__(NT, 1) k_fused(
    const int* __restrict__ inp,
    const float* __restrict__ hidden,
    const float* __restrict__ enc,
    const float* __restrict__ emb,
    const float* __restrict__ attn_W,
    const float* __restrict__ attn_b,
    const float* __restrict__ comb_W,
    const float* __restrict__ comb_b,
    const float* __restrict__ Wih,
    const float* __restrict__ Whh,
    const float* __restrict__ bih,
    const float* __restrict__ bhh,
    const float* __restrict__ out_W,
    const float* __restrict__ out_b,
    float* __restrict__ dout)
{
    __shared__ float sw[MAXLEN];
    __shared__ float spart[4][128];
    __shared__ float svec[HID];       // phase3: x ; phase4: h_new
    __shared__ float sm[NT], ss[NT];

    const int t = threadIdx.x;
    const int b = blockIdx.x;
    const int wid = t >> 5, lane = t & 31;
    const int GW = b * 16 + wid;

    const float4* h4 = (const float4*)hidden;

    // ======== Phase 0: attn logits (warps 0..63) || Whh gates (rest) ========
    if (b == 0 && t == 0) g_work = 0;   // reset work-steal counter (ordered by gsyncs)
    if (GW < 64) {
        const int row = GW;
        const float4* er4 = (const float4*)(emb + (size_t)inp[0] * HID);
        const float4* wr = (const float4*)(attn_W + (size_t)row * H2);
        float acc = 0.f;
#pragma unroll
        for (int i = 0; i < 16; i++) {
            int off = lane + 32 * i;
            float4 v = (i < 8) ? er4[off] : h4[off - 256];
            acc += dot4(wr[off], v);
        }
        acc = warp_sum(acc);
        if (lane == 0) g_logits[row] = acc + attn_b[row];
    } else {
        for (int r = GW - 64; r < H3; r += NW - 64) {
            const float4* wr = (const float4*)(Whh + (size_t)r * HID);
            float acc = 0.f;
#pragma unroll
            for (int i = 0; i < 8; i++) {
                int off = lane + 32 * i;
                acc += dot4(wr[off], h4[off]);
            }
            acc = warp_sum(acc);
            if (lane == 0) g_gh[r] = acc + bhh[r];
        }
    }
    gsync();

    // ======== Phase 1: softmax + attn_applied + cat (blocks 0..7) ========
    if (b < 8) {
        if (t < MAXLEN) sw[t] = g_logits[t];
        __syncthreads();
        if (t < 32) {
            float a = sw[t], c = sw[t + 32];
            float m = fmaxf(a, c);
#pragma unroll
            for (int o = 16; o; o >>= 1) m = fmaxf(m, __shfl_xor_sync(0xffffffffu, m, o));
            float e0 = __expf(a - m), e1 = __expf(c - m);
            float s = e0 + e1;
#pragma unroll
            for (int o = 16; o; o >>= 1) s += __shfl_xor_sync(0xffffffffu, s, o);
            sw[t] = e0 / s;
            sw[t + 32] = e1 / s;
            if (b == 0) {
                dout[VOCAB + HID + t] = sw[t];
                dout[VOCAB + HID + t + 32] = sw[t + 32];
            }
        }
        __syncthreads();
        int j = b * 128 + (t & 127);
        int isl = t >> 7;                 // 0..3
        float a = 0.f;
#pragma unroll
        for (int k = 0; k < 16; k++) {
            int i = isl + 4 * k;
            a += sw[i] * enc[i * HID + j];
        }
        spart[isl][t & 127] = a;
        __syncthreads();
        if (t < 128) {
            float s = spart[0][t] + spart[1][t] + spart[2][t] + spart[3][t];
            g_cat[HID + j] = s;
            g_cat[j] = emb[(size_t)inp[0] * HID + j];
        }
    }
    gsync();

    // ======== Phase 2: combine split-K=2 partials (2048 warps) ========
    if (GW < 2048) {
        int row = GW >> 1, half = GW & 1;
        const float4* wr = (const float4*)(comb_W + (size_t)row * H2) + half * 256;
        const float4* c4 = (const float4*)g_cat + half * 256;
        float acc = 0.f;
#pragma unroll
        for (int i = 0; i < 8; i++) {
            int off = lane + 32 * i;
            acc += dot4(wr[off], c4[off]);
        }
        acc = warp_sum(acc);
        if (lane == 0) g_xp[row + half * HID] = acc;
    }
    gsync();

    // ======== Phase 3: x = relu(p0+p1+b) (per-block smem) ; gi = Wih@x ========
    {
        for (int k = t; k < HID; k += NT)
            svec[k] = fmaxf(g_xp[k] + g_xp[k + HID] + comb_b[k], 0.f);
        __syncthreads();
        const float4* x4 = (const float4*)svec;
        for (int r = GW; r < H3; r += NW) {
            const float4* wr = (const float4*)(Wih + (size_t)r * HID);
            float acc = 0.f;
#pragma unroll
            for (int i = 0; i < 8; i++) {
                int off = lane + 32 * i;
                acc += dot4(wr[off], x4[off]);
            }
            acc = warp_sum(acc);
            if (lane == 0) g_gi[r] = acc + bih[r];
        }
    }
    gsync();

    // ======== Phase 4: h_new (redundant) + work-stealing out-proj GEMV ========
    __syncthreads();   // svec reuse: all phase-3 readers done (gsync above)
    for (int k = t; k < HID; k += NT) {
        float r = 1.f / (1.f + __expf(-(g_gi[k] + g_gh[k])));
        float z = 1.f / (1.f + __expf(-(g_gi[k + HID] + g_gh[k + HID])));
        float n = tanhf(g_gi[k + 2 * HID] + r * g_gh[k + 2 * HID]);
        float hnew = (1.f - z) * n + z * hidden[k];
        svec[k] = hnew;
        if (b == 0) dout[VOCAB + k] = hnew;
    }
    __syncthreads();
    {
        const float4* sv4 = (const float4*)svec;
        while (true) {
            int g;
            if (lane == 0) g = (int)atomicAdd(&g_work, 1u);
            g = __shfl_sync(0xffffffffu, g, 0);
            if (g >= NGROUPS) break;
            int row0 = g * 8;
            const float4* rp[8];
#pragma unroll
            for (int r = 0; r < 8; r++) {
                int row = row0 + r;
                if (row >= VOCAB) row = VOCAB - 1;
                rp[r] = (const float4*)(out_W + (size_t)row * HID);
            }
            float acc[8];
#pragma unroll
            for (int r = 0; r < 8; r++) acc[r] = 0.f;
#pragma unroll
            for (int i = 0; i < 8; i++) {
                int off = lane + 32 * i;
                float4 v = sv4[off];
#pragma unroll
                for (int r = 0; r < 8; r++) acc[r] += dot4(rp[r][off], v);
            }
#pragma unroll
            for (int r = 0; r < 8; r++) acc[r] = warp_sum(acc[r]);
            if (lane == 0) {
#pragma unroll
                for (int r = 0; r < 8; r++) {
                    int row = row0 + r;
                    if (row < VOCAB) dout[row] = acc[r] + out_b[row];
                }
            }
        }
    }
    gsync();

    // ======== Phase 5: per-block LSE partials over logits (L2 resident) ========
    {
        float m = BIG_NEG, s = 0.f;
        for (int i = b * NT + t; i < VOCAB; i += GRID * NT)
            lse_update(m, s, dout[i]);
        sm[t] = m;
        ss[t] = s;
        __syncthreads();
        for (int o = NT / 2; o; o >>= 1) {
            if (t < o) lse_merge(sm[t], ss[t], sm[t + o], ss[t + o]);
            __syncthreads();
        }
        if (t == 0) { g_pm[b] = sm[0]; g_ps[b] = ss[0]; }
    }
    gsync();

    // ======== Phase 6: merge partials (redundant) + subtract ========
    {
        float m = BIG_NEG, s = 0.f;
        if (t < GRID) { m = g_pm[t]; s = g_ps[t]; }
        sm[t] = m;
        ss[t] = s;
        __syncthreads();
        for (int o = 128; o; o >>= 1) {
            if (t < o) lse_merge(sm[t], ss[t], sm[t + o], ss[t + o]);
            __syncthreads();
        }
        float lse = sm[0] + __logf(ss[0]);
        for (int i = b * NT + t; i < VOCAB; i += GRID * NT) dout[i] -= lse;
    }
}

// ---------------- launcher ----------------
extern "C" void kernel_launch(void* const* d_in, const int* in_sizes, int n_in,
                              void* d_out, int out_size) {
    const int*   inp    = (const int*)d_in[0];
    const float* hidden = (const float*)d_in[1];
    const float* enc    = (const float*)d_in[2];
    const float* emb    = (const float*)d_in[3];
    const float* attn_W = (const float*)d_in[4];
    const float* attn_b = (const float*)d_in[5];
    const float* comb_W = (const float*)d_in[6];
    const float* comb_b = (const float*)d_in[7];
    const float* Wih    = (const float*)d_in[8];
    const float* Whh    = (const float*)d_in[9];
    const float* bih    = (const float*)d_in[10];
    const float* bhh    = (const float*)d_in[11];
    const float* out_W  = (const float*)d_in[12];
    const float* out_b  = (const float*)d_in[13];
    float* out = (float*)d_out;

    k_fused<<<GRID, NT>>>(inp, hidden, enc, emb, attn_W, attn_b,
                          comb_W, comb_b, Wih, Whh, bih, bhh,
                          out_W, out_b, out);
}